// round 12
// baseline (speedup 1.0000x reference)
#include <cuda_runtime.h>
#include <stdint.h>

// QuantizationLayer: out[i, 4j + k] = bit (3-k) of rint(x[i,j]*16 - 0.5), as f32.
// Champion config (R11) + 64-bit input loads:
//  - 2x ld.global.cg.v2.f32 per thread (L2-only, L2-resident across replays;
//    halves load-instr count vs 4x LDG.32 — float2 loads proven safe in R9)
//  - 2x 128-bit .cs stores (proven optimal width+policy)
//  - 4 elements/thread, TPB=256, one-shot grid, occ ~78%

#define TPB 256
#define PAIRS 2   // float2 pairs per thread -> 4 elements/thread

__device__ __forceinline__ float2 ldcg_f2(const float2* p)
{
    float2 v;
    asm volatile("ld.global.cg.v2.f32 {%0,%1}, [%2];"
                 : "=f"(v.x), "=f"(v.y) : "l"(p));
    return v;
}

__device__ __forceinline__ void quant4(float x, float4* b)
{
    // Match JAX exactly: two separate f32 ops, round-half-even.
    float t = x * 16.0f;
    t = t - 0.5f;
    int num = (int)rintf(t);
    num &= 255;  // uint8 wraparound emulation (no-op for x in [0,1))

    b->x = (num & 8) ? 1.0f : 0.0f;
    b->y = (num & 4) ? 1.0f : 0.0f;
    b->z = (num & 2) ? 1.0f : 0.0f;
    b->w = (num & 1) ? 1.0f : 0.0f;
}

__global__ void __launch_bounds__(TPB, 8)
quant_bits_kernel(const float2* __restrict__ x2, float* __restrict__ out, int n_pairs)
{
    int base = blockIdx.x * (TPB * PAIRS) + threadIdx.x;
    float4* out4 = reinterpret_cast<float4*>(out);

    // Front-batched independent 64-bit L2-cached loads.
    float2 v[PAIRS];
#pragma unroll
    for (int u = 0; u < PAIRS; u++) {
        int p = base + u * TPB;
        v[u] = (p < n_pairs) ? ldcg_f2(&x2[p]) : make_float2(0.0f, 0.0f);
    }

#pragma unroll
    for (int u = 0; u < PAIRS; u++) {
        int p = base + u * TPB;
        if (p >= n_pairs) continue;

        float4 lo, hi;
        quant4(v[u].x, &lo);
        quant4(v[u].y, &hi);

        __stcs(out4 + (size_t)p * 2,     lo);   // 128-bit evict-first stores
        __stcs(out4 + (size_t)p * 2 + 1, hi);
    }
}

extern "C" void kernel_launch(void* const* d_in, const int* in_sizes, int n_in,
                              void* d_out, int out_size)
{
    const float2* x2 = (const float2*)d_in[0];
    float* out = (float*)d_out;
    int n_pairs = in_sizes[0] / 2;   // 8388608 / 2 = 4194304

    int blocks = (n_pairs + TPB * PAIRS - 1) / (TPB * PAIRS);
    quant_bits_kernel<<<blocks, TPB>>>(x2, out, n_pairs);
}

// round 13
// speedup vs baseline: 1.4106x; 1.4106x over previous
#include <cuda_runtime.h>
#include <stdint.h>

// QuantizationLayer: out[i, 4j + k] = bit (3-k) of rint(x[i,j]*16 - 0.5), as f32.
// CHAMPION CONFIG (R11, 25.1us) — exact revert of the R12 experiment.
// Design-space map (all measured):
//   store width : 128-bit .cs BEST (256-bit hurts replay; .wt hurts; default hurts)
//   load policy : __ldcg BEST (skip per-launch-flushed L1, stay L2-resident
//                 across graph replays); __ldcs forfeits replay reuse
//   indexing    : block-strided scalar — ONLY layout where both load (4B/lane
//                 dense) and store (16B/lane dense) streams fully coalesce
//   unroll=4, TPB=256, one-shot exact grid, occ ~78%
// Residual time is mandatory 128MB/replay DRAM write drain (~5.1 TB/s eff).

#define TPB 256
#define UNROLL 4

__global__ void __launch_bounds__(TPB, 8)
quant_bits_kernel(const float* __restrict__ x, float* __restrict__ out, int n)
{
    int base = blockIdx.x * (TPB * UNROLL) + threadIdx.x;
    float4* out4 = reinterpret_cast<float4*>(out);

    // Front-batched independent L2-cached loads (skip L1; L2-resident across replays).
    float v[UNROLL];
#pragma unroll
    for (int u = 0; u < UNROLL; u++) {
        int i = base + u * TPB;
        v[u] = (i < n) ? __ldcg(&x[i]) : 0.0f;
    }

#pragma unroll
    for (int u = 0; u < UNROLL; u++) {
        int i = base + u * TPB;
        if (i >= n) continue;

        // Match JAX exactly: two separate f32 ops, round-half-even.
        float t = v[u] * 16.0f;
        t = t - 0.5f;
        int num = (int)rintf(t);
        num &= 255;  // uint8 wraparound emulation (no-op for x in [0,1))

        float4 bits;
        bits.x = (num & 8) ? 1.0f : 0.0f;
        bits.y = (num & 4) ? 1.0f : 0.0f;
        bits.z = (num & 2) ? 1.0f : 0.0f;
        bits.w = (num & 1) ? 1.0f : 0.0f;
        __stcs(out4 + i, bits);   // evict-first: don't displace L2-resident input
    }
}

extern "C" void kernel_launch(void* const* d_in, const int* in_sizes, int n_in,
                              void* d_out, int out_size)
{
    const float* x = (const float*)d_in[0];
    float* out = (float*)d_out;
    int n = in_sizes[0];   // 4096 * 2048 = 8388608

    int blocks = (n + TPB * UNROLL - 1) / (TPB * UNROLL);
    quant_bits_kernel<<<blocks, TPB>>>(x, out, n);
}